// round 7
// baseline (speedup 1.0000x reference)
#include <cuda_runtime.h>
#include <cuda_fp16.h>
#include <math.h>
#include <stdint.h>

// ===========================================================================
// SwinV2 block. GEMMs via mma.sync (HMMA) fp16, 2-segment split
// (A=[hi|lo], B=[hi|hi] -> computes a*b_hi exactly; error ~2^-12),
// fp32 accumulation. CTA 128x128, 4 warps of 64x64, 3-stage cp.async,
// 2 CTAs/SM.
// ===========================================================================

#define LN100 4.6051701859880914f

// ------------------------- scratch (device globals) ------------------------
__device__ __align__(128) __half g_xg2[67108864];    // [32768][2048] A qkv
__device__ __align__(128) __half g_w2[25165824];     // split weights
__device__ __align__(128) __half g_attn2[67108864];  // [32768][2048] A proj
__device__ __align__(128) __half g_out2[67108864];   // [32768][2048] A fc1
__device__ __align__(128) __half g_h2[268435456];    // [32768][8192] A fc2
__device__ __align__(128) float g_qkv[100663296];    // [3][512][16][64][64]
__device__ __align__(128) float g_proj[33554432];
__device__ __align__(128) float g_mlp[33554432];
__device__ float g_tbl[3600];

#define W2_QKV  0
#define W2_PROJ 6291456
#define W2_FC1  8388608
#define W2_FC2  16777216

__device__ __forceinline__ int winmap(int wr) {
    int wt = wr >> 6, t = wr & 63;
    int img = wt >> 2, wi = wt & 3;
    int r = (((wi >> 1) << 3) + (t >> 3) + 4) & 15;
    int c = (((wi & 1) << 3) + (t & 7) + 4) & 15;
    return (img << 8) + (r << 4) + c;
}

// ---------------------------- PTX helpers -----------------------------------
__device__ __forceinline__ uint32_t smem_u32(const void* p) {
    uint32_t a;
    asm("{ .reg .u64 t; cvta.to.shared.u64 t, %1; cvt.u32.u64 %0, t; }"
        : "=r"(a) : "l"(p));
    return a;
}
__device__ __forceinline__ void cp16(uint32_t s, const void* g) {
    asm volatile("cp.async.cg.shared.global [%0], [%1], 16;" :: "r"(s), "l"(g));
}
#define CP_COMMIT() asm volatile("cp.async.commit_group;" ::: "memory")
#define CP_WAIT1()  asm volatile("cp.async.wait_group 1;" ::: "memory")

__device__ __forceinline__ void ldmx4(uint32_t a, uint32_t& r0, uint32_t& r1,
                                      uint32_t& r2, uint32_t& r3) {
    asm volatile("ldmatrix.sync.aligned.m8n8.x4.shared.b16 {%0,%1,%2,%3}, [%4];"
                 : "=r"(r0), "=r"(r1), "=r"(r2), "=r"(r3) : "r"(a));
}
__device__ __forceinline__ void mma16816(float* c, const uint32_t* a,
                                         const uint32_t* b) {
    asm volatile(
        "mma.sync.aligned.m16n8k16.row.col.f32.f16.f16.f32 "
        "{%0,%1,%2,%3}, {%4,%5,%6,%7}, {%8,%9}, {%0,%1,%2,%3};"
        : "+f"(c[0]), "+f"(c[1]), "+f"(c[2]), "+f"(c[3])
        : "r"(a[0]), "r"(a[1]), "r"(a[2]), "r"(a[3]), "r"(b[0]), "r"(b[1]));
}

__device__ __forceinline__ void hf_split(float v, __half& hi, __half& lo) {
    hi = __float2half_rn(v);
    lo = __float2half_rn(v - __half2float(hi));
}

// ------------------------------- HMMA GEMM ----------------------------------
// C[M,N] = A[M,K2] * B[N,K2]^T, both fp16 row-major (K contiguous).
// CTA 128x128, BK=32, 3 stages cp.async, 4 warps of 64x64, 2 CTAs/SM.
// MODE 0: QKV scatter (+q/v bias) -> g_qkv fp32
// MODE 1: +bias -> Cf fp32
// MODE 2: +bias +exact GELU -> g_h2 fp16 split (hi|lo)
// MODE 3: +bias -> Cf fp32
#define SPITCH 80
#define ATILE  10240           // 128*80
#define STAGEB 20480           // A + B

template <int MODE>
__global__ void __launch_bounds__(128, 2) mma_gemm(
    const __half* __restrict__ A, const __half* __restrict__ B,
    const float* __restrict__ bias, const float* __restrict__ bias2,
    float* __restrict__ Cf, int K2, int N)
{
    extern __shared__ __align__(128) char sm[];
    const uint32_t smu = smem_u32(sm);
    const int tid = threadIdx.x;
    const int lane = tid & 31, w = tid >> 5;
    const int warpM = w >> 1, warpN = w & 1;
    const int row0 = blockIdx.y * 128, col0 = blockIdx.x * 128;

    // ---- cp.async: thread covers rows r1, r1+64 of A and B, 2 chunks each --
    const int r1 = tid >> 1;                  // 0..63
    const int kc = (tid & 1) * 2;             // chunk pair 0-1 or 2-3 (16B each)
    const __half* Ag0 = A + (size_t)(row0 + r1) * K2 + kc * 8;
    const __half* Ag1 = Ag0 + (size_t)64 * K2;
    const __half* Bg0 = B + (size_t)(col0 + r1) * K2 + kc * 8;
    const __half* Bg1 = Bg0 + (size_t)64 * K2;
    const uint32_t sd0 = (uint32_t)(r1 * SPITCH + kc * 16);
    const uint32_t sd1 = sd0 + 64 * SPITCH;

    // ---- ldmatrix lane offsets (within stage) ----
    const uint32_t aoff =
        (uint32_t)((warpM * 64 + (lane & 7) + ((lane >> 3) & 1) * 8) * SPITCH +
                   ((lane >> 4) & 1) * 16);
    const uint32_t boff =
        (uint32_t)(ATILE + (warpN * 64 + (lane & 7) + ((lane >> 4) & 1) * 8) * SPITCH +
                   ((lane >> 3) & 1) * 16);

    float acc[32][4];
#pragma unroll
    for (int i = 0; i < 32; i++)
#pragma unroll
        for (int j = 0; j < 4; j++) acc[i][j] = 0.f;

    const int T = K2 >> 5;

    // prologue: stages 0,1
#pragma unroll
    for (int s = 0; s < 2; s++) {
        const uint32_t sb = smu + s * STAGEB;
        const size_t ko = (size_t)s * 32;
        cp16(sb + sd0,      Ag0 + ko);
        cp16(sb + sd0 + 16, Ag0 + ko + 8);
        cp16(sb + sd1,      Ag1 + ko);
        cp16(sb + sd1 + 16, Ag1 + ko + 8);
        cp16(sb + ATILE + sd0,      Bg0 + ko);
        cp16(sb + ATILE + sd0 + 16, Bg0 + ko + 8);
        cp16(sb + ATILE + sd1,      Bg1 + ko);
        cp16(sb + ATILE + sd1 + 16, Bg1 + ko + 8);
        CP_COMMIT();
    }

    for (int kt = 0; kt < T; ++kt) {
        CP_WAIT1();
        __syncthreads();

        if (kt + 2 < T) {
            const uint32_t sb = smu + ((kt + 2) % 3) * STAGEB;
            const size_t ko = (size_t)(kt + 2) * 32;
            cp16(sb + sd0,      Ag0 + ko);
            cp16(sb + sd0 + 16, Ag0 + ko + 8);
            cp16(sb + sd1,      Ag1 + ko);
            cp16(sb + sd1 + 16, Ag1 + ko + 8);
            cp16(sb + ATILE + sd0,      Bg0 + ko);
            cp16(sb + ATILE + sd0 + 16, Bg0 + ko + 8);
            cp16(sb + ATILE + sd1,      Bg1 + ko);
            cp16(sb + ATILE + sd1 + 16, Bg1 + ko + 8);
        }
        CP_COMMIT();

        const uint32_t base = smu + (kt % 3) * STAGEB;
#pragma unroll
        for (int kk = 0; kk < 2; kk++) {
            uint32_t bf[8][2];
#pragma unroll
            for (int p = 0; p < 4; p++)
                ldmx4(base + boff + p * 16 * SPITCH + kk * 32,
                      bf[2 * p][0], bf[2 * p][1], bf[2 * p + 1][0], bf[2 * p + 1][1]);
#pragma unroll
            for (int mt = 0; mt < 4; mt++) {
                uint32_t af[4];
                ldmx4(base + aoff + mt * 16 * SPITCH + kk * 32,
                      af[0], af[1], af[2], af[3]);
#pragma unroll
                for (int nt = 0; nt < 8; nt++)
                    mma16816(acc[mt * 8 + nt], af, bf[nt]);
            }
        }
    }

    // ------------------------------ epilogue --------------------------------
#pragma unroll
    for (int mt = 0; mt < 4; mt++) {
#pragma unroll
        for (int nt = 0; nt < 8; nt++) {
            const float* c = acc[mt * 8 + nt];
            const int col = col0 + warpN * 64 + nt * 8 + (lane & 3) * 2;
#pragma unroll
            for (int half = 0; half < 2; half++) {
                const int row = row0 + warpM * 64 + mt * 16 + (lane >> 2) + half * 8;
                const float v0 = c[half * 2 + 0], v1 = c[half * 2 + 1];
                if (MODE == 0) {
                    const int which = col >> 10, rem = col & 1023;
                    const float* bs = (which == 0) ? bias : (which == 2) ? bias2 : nullptr;
                    const float b0 = bs ? bs[rem] : 0.f, b1 = bs ? bs[rem + 1] : 0.f;
                    float* dst = g_qkv + (size_t)which * 33554432 +
                                 (size_t)(row >> 6) * 65536 + (rem >> 6) * 4096 +
                                 (row & 63) * 64 + (rem & 63);
                    *(float2*)dst = make_float2(v0 + b0, v1 + b1);
                } else if (MODE == 2) {
                    float s0 = v0 + bias[col], s1 = v1 + bias[col + 1];
                    s0 = 0.5f * s0 * (1.0f + erff(s0 * 0.70710678118654752f));
                    s1 = 0.5f * s1 * (1.0f + erff(s1 * 0.70710678118654752f));
                    __half h0, l0, h1, l1;
                    hf_split(s0, h0, l0);
                    hf_split(s1, h1, l1);
                    __half2 hh, ll;
                    hh.x = h0; hh.y = h1; ll.x = l0; ll.y = l1;
                    __half* dst = g_h2 + (size_t)row * 8192 + col;
                    *(__half2*)(dst) = hh;
                    *(__half2*)(dst + 4096) = ll;
                } else {
                    float* dst = Cf + (size_t)row * N + col;
                    *(float2*)dst = make_float2(v0 + bias[col], v1 + bias[col + 1]);
                }
            }
        }
    }
}

// ------------------------- split / gather kernels ---------------------------
// A-order: [hi | lo]; gathers x via winmap
__global__ void __launch_bounds__(256) xsplit_kernel(const float* __restrict__ x)
{
    const int wr = blockIdx.x;
    const int g = winmap(wr);
    const float4 v = *(const float4*)(x + (size_t)g * 1024 + threadIdx.x * 4);
    const float f[4] = {v.x, v.y, v.z, v.w};
    __half h[4], l[4];
#pragma unroll
    for (int j = 0; j < 4; j++) hf_split(f[j], h[j], l[j]);
    __half* dst = g_xg2 + (size_t)wr * 2048 + threadIdx.x * 4;
    __half2 h01, h23, l01, l23;
    h01.x = h[0]; h01.y = h[1]; h23.x = h[2]; h23.y = h[3];
    l01.x = l[0]; l01.y = l[1]; l23.x = l[2]; l23.y = l[3];
    *(__half2*)(dst) = h01;          *(__half2*)(dst + 2) = h23;
    *(__half2*)(dst + 1024) = l01;   *(__half2*)(dst + 1026) = l23;
}

// B-order: [hi | hi]
__global__ void __launch_bounds__(256) wsplit_kernel(
    const float* __restrict__ src, __half* __restrict__ dst, int K)
{
    const int row = blockIdx.x;
    const float* s = src + (size_t)row * K;
    __half* d = dst + (size_t)row * 2 * K;
    for (int c = threadIdx.x * 4; c < K; c += 1024) {
        const float4 v = *(const float4*)(s + c);
        __half h[4];
        h[0] = __float2half_rn(v.x); h[1] = __float2half_rn(v.y);
        h[2] = __float2half_rn(v.z); h[3] = __float2half_rn(v.w);
        __half2 h01, h23;
        h01.x = h[0]; h01.y = h[1]; h23.x = h[2]; h23.y = h[3];
        *(__half2*)(d + c) = h01;         *(__half2*)(d + c + 2) = h23;
        *(__half2*)(d + K + c) = h01;     *(__half2*)(d + K + c + 2) = h23;
    }
}

// --------------------------- CPB bias table ---------------------------------
__global__ void cpb_kernel(const float* __restrict__ w1,
                           const float* __restrict__ b1,
                           const float* __restrict__ w2)
{
    __shared__ float hbuf[512];
    const int p = blockIdx.x;
    const int a = p / 15, b = p % 15;
    const float va = (a - 7) * (1.0f / 7.0f), vb = (b - 7) * (1.0f / 7.0f);
    const float c0 = (va > 0.f ? 1.f : (va < 0.f ? -1.f : 0.f)) * log2f(1.f + fabsf(va));
    const float c1 = (vb > 0.f ? 1.f : (vb < 0.f ? -1.f : 0.f)) * log2f(1.f + fabsf(vb));
    const int j = threadIdx.x;
    float hv = w1[j * 2] * c0 + w1[j * 2 + 1] * c1 + b1[j];
    hbuf[j] = fmaxf(hv, 0.f);
    __syncthreads();
    if (j < 16) {
        float s = 0.f;
        for (int t = 0; t < 512; t++) s += hbuf[t] * w2[j * 512 + t];
        g_tbl[p * 16 + j] = 16.f / (1.f + expf(-s));
    }
}

// ------------------------------ attention -----------------------------------
__global__ void __launch_bounds__(256) attn_kernel(const float* __restrict__ ls)
{
    __shared__ float sA[64 * 68];
    __shared__ float sB[64 * 65];
    __shared__ float rn[128];

    const int h = blockIdx.x, wt = blockIdx.y;
    const int tid = threadIdx.x;
    const float* qg = g_qkv + (size_t)wt * 65536 + h * 4096;
    const float* kg = qg + 33554432;
    const float* vg = qg + 67108864;

#pragma unroll
    for (int i = 0; i < 4; i++) {
        int v4 = tid + 256 * i;
        int r = v4 >> 4, c4 = v4 & 15;
        *(float4*)&sA[r * 68 + c4 * 4] = *(const float4*)(qg + v4 * 4);
    }
#pragma unroll
    for (int i = 0; i < 16; i++) {
        int idx = tid + 256 * i;
        sB[(idx >> 6) * 65 + (idx & 63)] = kg[idx];
    }
    __syncthreads();

    {
        const int r = tid >> 2, part = tid & 3;
        float sq = 0.f, sk = 0.f;
#pragma unroll
        for (int j = 0; j < 16; j++) {
            float xq = sA[r * 68 + part + 4 * j]; sq += xq * xq;
            float xk = sB[r * 65 + part + 4 * j]; sk += xk * xk;
        }
        sq += __shfl_xor_sync(0xffffffffu, sq, 1);
        sq += __shfl_xor_sync(0xffffffffu, sq, 2);
        sk += __shfl_xor_sync(0xffffffffu, sk, 1);
        sk += __shfl_xor_sync(0xffffffffu, sk, 2);
        if (part == 0) {
            rn[r]      = 1.f / fmaxf(sqrtf(sq), 1e-12f);
            rn[64 + r] = 1.f / fmaxf(sqrtf(sk), 1e-12f);
        }
    }
    __syncthreads();

    const float scale = expf(fminf(ls[h], LN100));
    const int wi = wt & 3;
    const int m = tid & 63;
    const int nbase = tid >> 6;

    float kreg[64];
#pragma unroll
    for (int kk = 0; kk < 64; kk++) kreg[kk] = sB[m * 65 + kk];

    const int srm = ((wi >> 1) << 3) + (m >> 3), scm = ((wi & 1) << 3) + (m & 7);
    const int rgm = (srm < 8 ? 0 : (srm < 12 ? 1 : 2)) * 3 +
                    (scm < 8 ? 0 : (scm < 12 ? 1 : 2));

    float sc[16];
#pragma unroll
    for (int i = 0; i < 16; i++) {
        const int n = nbase + 4 * i;
        float dot = 0.f;
#pragma unroll
        for (int k4 = 0; k4 < 16; k4++) {
            float4 qv = *(const float4*)&sA[n * 68 + k4 * 4];
            dot += qv.x * kreg[k4 * 4] + qv.y * kreg[k4 * 4 + 1] +
                   qv.z * kreg[k4 * 4 + 2] + qv.w * kreg[k4 * 4 + 3];
        }
        dot *= rn[n] * rn[64 + m] * scale;
        const int idx = ((n >> 3) - (m >> 3) + 7) * 15 + ((n & 7) - (m & 7) + 7);
        dot += g_tbl[idx * 16 + h];
        const int srn = ((wi >> 1) << 3) + (n >> 3), scn = ((wi & 1) << 3) + (n & 7);
        const int rgn = (srn < 8 ? 0 : (srn < 12 ? 1 : 2)) * 3 +
                        (scn < 8 ? 0 : (scn < 12 ? 1 : 2));
        if (rgn != rgm) dot -= 100.f;
        sc[i] = dot;
    }
    __syncthreads();

#pragma unroll
    for (int i = 0; i < 16; i++) sA[(nbase + 4 * i) * 68 + m] = sc[i];
#pragma unroll
    for (int i = 0; i < 16; i++) {
        int idx = tid + 256 * i;
        sB[(idx >> 6) * 65 + (idx & 63)] = vg[idx];
    }
    __syncthreads();

    {
        const int r = tid >> 2, part = tid & 3;
        float mx = -1e30f;
#pragma unroll
        for (int j = 0; j < 16; j++) mx = fmaxf(mx, sA[r * 68 + part + 4 * j]);
        mx = fmaxf(mx, __shfl_xor_sync(0xffffffffu, mx, 1));
        mx = fmaxf(mx, __shfl_xor_sync(0xffffffffu, mx, 2));
        float sum = 0.f;
#pragma unroll
        for (int j = 0; j < 16; j++) {
            float e = expf(sA[r * 68 + part + 4 * j] - mx);
            sA[r * 68 + part + 4 * j] = e;
            sum += e;
        }
        sum += __shfl_xor_sync(0xffffffffu, sum, 1);
        sum += __shfl_xor_sync(0xffffffffu, sum, 2);
        const float inv = 1.f / sum;
#pragma unroll
        for (int j = 0; j < 16; j++) sA[r * 68 + part + 4 * j] *= inv;
    }
    __syncthreads();

    const int d = tid & 63;
    float vreg[64];
#pragma unroll
    for (int mm = 0; mm < 64; mm++) vreg[mm] = sB[mm * 65 + d];
#pragma unroll
    for (int i = 0; i < 16; i++) {
        const int n = nbase + 4 * i;
        float o = 0.f;
#pragma unroll
        for (int m4 = 0; m4 < 16; m4++) {
            float4 pv = *(const float4*)&sA[n * 68 + m4 * 4];
            o += pv.x * vreg[m4 * 4] + pv.y * vreg[m4 * 4 + 1] +
                 pv.z * vreg[m4 * 4 + 2] + pv.w * vreg[m4 * 4 + 3];
        }
        __half hi, lo;
        hf_split(o, hi, lo);
        const size_t base = (size_t)(wt * 64 + n) * 2048 + h * 64 + d;
        g_attn2[base] = hi;
        g_attn2[base + 1024] = lo;
    }
}

// --------------------------- LN kernels --------------------------------------
__device__ __forceinline__ float2 block_reduce2(float s, float q, float* red)
{
#pragma unroll
    for (int o = 16; o; o >>= 1) {
        s += __shfl_xor_sync(0xffffffffu, s, o);
        q += __shfl_xor_sync(0xffffffffu, q, o);
    }
    const int w = threadIdx.x >> 5;
    if ((threadIdx.x & 31) == 0) { red[w] = s; red[8 + w] = q; }
    __syncthreads();
    s = red[threadIdx.x & 7];
    q = red[8 + (threadIdx.x & 7)];
#pragma unroll
    for (int o = 4; o; o >>= 1) {
        s += __shfl_xor_sync(0xffffffffu, s, o);
        q += __shfl_xor_sync(0xffffffffu, q, o);
    }
    return make_float2(s, q);
}

// xs1[g] = x[g] + LN(proj[wr]); also emits fp16 split rows for fc1 A
__global__ void __launch_bounds__(256) lnscatter_kernel(
    const float* __restrict__ x, const float* __restrict__ w,
    const float* __restrict__ b, float* __restrict__ out)
{
    __shared__ float red[16];
    const int wr = blockIdx.x;
    const int g = winmap(wr);
    const float* p = g_proj + (size_t)wr * 1024;
    float vv[4], s = 0.f, q = 0.f;
#pragma unroll
    for (int i = 0; i < 4; i++) {
        vv[i] = p[threadIdx.x + 256 * i];
        s += vv[i]; q += vv[i] * vv[i];
    }
    float2 t = block_reduce2(s, q, red);
    const float mean = t.x * (1.f / 1024.f);
    const float var = t.y * (1.f / 1024.f) - mean * mean;
    const float rs = rsqrtf(var + 1e-5f);
    const float* xr = x + (size_t)g * 1024;
    float* orow = out + (size_t)g * 1024;
    __half* drow = g_out2 + (size_t)g * 2048;
#pragma unroll
    for (int i = 0; i < 4; i++) {
        const int c = threadIdx.x + 256 * i;
        const float val = xr[c] + (vv[i] - mean) * rs * w[c] + b[c];
        orow[c] = val;
        __half hi, lo;
        hf_split(val, hi, lo);
        drow[c] = hi;
        drow[1024 + c] = lo;
    }
}

// out[tok] += LN(mlp[tok])
__global__ void __launch_bounds__(256) lnadd_kernel(
    const float* __restrict__ w, const float* __restrict__ b,
    float* __restrict__ out)
{
    __shared__ float red[16];
    const int tok = blockIdx.x;
    const float* p = g_mlp + (size_t)tok * 1024;
    float vv[4], s = 0.f, q = 0.f;
#pragma unroll
    for (int i = 0; i < 4; i++) {
        vv[i] = p[threadIdx.x + 256 * i];
        s += vv[i]; q += vv[i] * vv[i];
    }
    float2 t = block_reduce2(s, q, red);
    const float mean = t.x * (1.f / 1024.f);
    const float var = t.y * (1.f / 1024.f) - mean * mean;
    const float rs = rsqrtf(var + 1e-5f);
    float* orow = out + (size_t)tok * 1024;
#pragma unroll
    for (int i = 0; i < 4; i++) {
        const int c = threadIdx.x + 256 * i;
        orow[c] += (vv[i] - mean) * rs * w[c] + b[c];
    }
}

// ------------------------------- launcher -----------------------------------
extern "C" void kernel_launch(void* const* d_in, const int* in_sizes, int n_in,
                              void* d_out, int out_size)
{
    const float* x      = (const float*)d_in[0];
    const float* qkv_w  = (const float*)d_in[1];
    const float* q_bias = (const float*)d_in[2];
    const float* v_bias = (const float*)d_in[3];
    const float* lscale = (const float*)d_in[4];
    const float* cpb_w1 = (const float*)d_in[5];
    const float* cpb_b1 = (const float*)d_in[6];
    const float* cpb_w2 = (const float*)d_in[7];
    const float* proj_w = (const float*)d_in[8];
    const float* proj_b = (const float*)d_in[9];
    const float* n1w    = (const float*)d_in[10];
    const float* n1b    = (const float*)d_in[11];
    const float* fc1_w  = (const float*)d_in[12];
    const float* fc1_b  = (const float*)d_in[13];
    const float* fc2_w  = (const float*)d_in[14];
    const float* fc2_b  = (const float*)d_in[15];
    const float* n2w    = (const float*)d_in[16];
    const float* n2b    = (const float*)d_in[17];
    float* out = (float*)d_out;

    __half *p_xg2, *p_w2, *p_attn2, *p_out2, *p_h2;
    float *p_proj, *p_mlp;
    cudaGetSymbolAddress((void**)&p_xg2,   g_xg2);
    cudaGetSymbolAddress((void**)&p_w2,    g_w2);
    cudaGetSymbolAddress((void**)&p_attn2, g_attn2);
    cudaGetSymbolAddress((void**)&p_out2,  g_out2);
    cudaGetSymbolAddress((void**)&p_h2,    g_h2);
    cudaGetSymbolAddress((void**)&p_proj,  g_proj);
    cudaGetSymbolAddress((void**)&p_mlp,   g_mlp);

    const int SMEMSZ = 3 * STAGEB;  // 61440
    cudaFuncSetAttribute(mma_gemm<0>, cudaFuncAttributeMaxDynamicSharedMemorySize, SMEMSZ);
    cudaFuncSetAttribute(mma_gemm<1>, cudaFuncAttributeMaxDynamicSharedMemorySize, SMEMSZ);
    cudaFuncSetAttribute(mma_gemm<2>, cudaFuncAttributeMaxDynamicSharedMemorySize, SMEMSZ);
    cudaFuncSetAttribute(mma_gemm<3>, cudaFuncAttributeMaxDynamicSharedMemorySize, SMEMSZ);

    cpb_kernel<<<225, 512>>>(cpb_w1, cpb_b1, cpb_w2);
    xsplit_kernel<<<32768, 256>>>(x);
    wsplit_kernel<<<3072, 256>>>(qkv_w, p_w2 + W2_QKV, 1024);
    wsplit_kernel<<<1024, 256>>>(proj_w, p_w2 + W2_PROJ, 1024);
    wsplit_kernel<<<4096, 256>>>(fc1_w, p_w2 + W2_FC1, 1024);
    wsplit_kernel<<<1024, 256>>>(fc2_w, p_w2 + W2_FC2, 4096);

    // QKV: M=32768, N=3072, K'=2048
    mma_gemm<0><<<dim3(24, 256), 128, SMEMSZ>>>(
        p_xg2, p_w2 + W2_QKV, q_bias, v_bias, nullptr, 2048, 3072);

    attn_kernel<<<dim3(16, 512), 256>>>(lscale);

    // proj: N=1024, K'=2048
    mma_gemm<1><<<dim3(8, 256), 128, SMEMSZ>>>(
        p_attn2, p_w2 + W2_PROJ, proj_b, nullptr, p_proj, 2048, 1024);

    lnscatter_kernel<<<32768, 256>>>(x, n1w, n1b, out);

    // fc1 + GELU: N=4096, K'=2048
    mma_gemm<2><<<dim3(32, 256), 128, SMEMSZ>>>(
        p_out2, p_w2 + W2_FC1, fc1_b, nullptr, nullptr, 2048, 4096);

    // fc2: N=1024, K'=8192
    mma_gemm<3><<<dim3(8, 256), 128, SMEMSZ>>>(
        p_h2, p_w2 + W2_FC2, fc2_b, nullptr, p_mlp, 8192, 1024);

    lnadd_kernel<<<32768, 256>>>(n2w, n2b, out);
}

// round 8
// speedup vs baseline: 1.1037x; 1.1037x over previous
#include <cuda_runtime.h>
#include <cuda_fp16.h>
#include <math.h>
#include <stdint.h>

// ===========================================================================
// SwinV2 block. GEMMs via mma.sync (HMMA) fp16, 2-segment split:
// A=[hi|lo] (row stride 2K), B=[hi] single copy. Mainloop over real K with
// stage tiles [A_hi | A_lo | B]; B fragments reused for both A segments.
// CTA 128x128, 8 warps of 64x32, 3-stage cp.async, 2 CTAs/SM.
// ===========================================================================

#define LN100 4.6051701859880914f

// ------------------------- scratch (device globals) ------------------------
__device__ __align__(128) __half g_xg2[67108864];    // [32768][2048] A qkv (hi|lo)
__device__ __align__(128) __half g_w2[12582912];     // weights, hi only
__device__ __align__(128) __half g_attn2[67108864];  // [32768][2048] A proj
__device__ __align__(128) __half g_out2[67108864];   // [32768][2048] A fc1
__device__ __align__(128) __half g_h2[268435456];    // [32768][8192] A fc2
__device__ __align__(128) float g_qkv[100663296];    // [3][512][16][64][64]
__device__ __align__(128) float g_proj[33554432];
__device__ __align__(128) float g_mlp[33554432];
__device__ float g_tbl[3600];

#define W2_QKV  0
#define W2_PROJ 3145728
#define W2_FC1  4194304
#define W2_FC2  8388608

__device__ __forceinline__ int winmap(int wr) {
    int wt = wr >> 6, t = wr & 63;
    int img = wt >> 2, wi = wt & 3;
    int r = (((wi >> 1) << 3) + (t >> 3) + 4) & 15;
    int c = (((wi & 1) << 3) + (t & 7) + 4) & 15;
    return (img << 8) + (r << 4) + c;
}

// ---------------------------- PTX helpers -----------------------------------
__device__ __forceinline__ uint32_t smem_u32(const void* p) {
    uint32_t a;
    asm("{ .reg .u64 t; cvta.to.shared.u64 t, %1; cvt.u32.u64 %0, t; }"
        : "=r"(a) : "l"(p));
    return a;
}
__device__ __forceinline__ void cp16(uint32_t s, const void* g) {
    asm volatile("cp.async.cg.shared.global [%0], [%1], 16;" :: "r"(s), "l"(g));
}
#define CP_COMMIT() asm volatile("cp.async.commit_group;" ::: "memory")
#define CP_WAIT1()  asm volatile("cp.async.wait_group 1;" ::: "memory")

__device__ __forceinline__ void ldmx4(uint32_t a, uint32_t& r0, uint32_t& r1,
                                      uint32_t& r2, uint32_t& r3) {
    asm volatile("ldmatrix.sync.aligned.m8n8.x4.shared.b16 {%0,%1,%2,%3}, [%4];"
                 : "=r"(r0), "=r"(r1), "=r"(r2), "=r"(r3) : "r"(a));
}
__device__ __forceinline__ void mma16816(float* c, const uint32_t* a,
                                         const uint32_t* b) {
    asm volatile(
        "mma.sync.aligned.m16n8k16.row.col.f32.f16.f16.f32 "
        "{%0,%1,%2,%3}, {%4,%5,%6,%7}, {%8,%9}, {%0,%1,%2,%3};"
        : "+f"(c[0]), "+f"(c[1]), "+f"(c[2]), "+f"(c[3])
        : "r"(a[0]), "r"(a[1]), "r"(a[2]), "r"(a[3]), "r"(b[0]), "r"(b[1]));
}

__device__ __forceinline__ void hf_split(float v, __half& hi, __half& lo) {
    hi = __float2half_rn(v);
    lo = __float2half_rn(v - __half2float(hi));
}

// ------------------------------- HMMA GEMM ----------------------------------
// C[M,N] = (A_hi + A_lo)[M,K] * B_hi[N,K]^T.
// A rows: [hi(K) | lo(K)], stride 2K. B rows: hi only, stride K.
// Stage = [A_hi 128x32 | A_lo 128x32 | B 128x32], 30720 B. 3 stages.
// MODE 0: QKV scatter (+q/v bias) -> g_qkv fp32
// MODE 1: +bias -> Cf fp32
// MODE 2: +bias +exact GELU -> g_h2 fp16 split (hi|lo)
// MODE 3: +bias -> Cf fp32
#define SPITCH 80
#define TILEB  10240           // 128*80
#define STAGEB 30720           // A_hi + A_lo + B

template <int MODE>
__global__ void __launch_bounds__(256, 2) mma_gemm(
    const __half* __restrict__ A, const __half* __restrict__ B,
    const float* __restrict__ bias, const float* __restrict__ bias2,
    float* __restrict__ Cf, int K, int N)
{
    extern __shared__ __align__(128) char sm[];
    const uint32_t smu = smem_u32(sm);
    const int tid = threadIdx.x;
    const int lane = tid & 31, w = tid >> 5;
    const int warpM = w >> 2, warpN = w & 3;
    const int row0 = blockIdx.y * 128, col0 = blockIdx.x * 128;

    // ---- cp.async: thread covers one row of each tile, 2x16B chunks --------
    const int r1 = tid >> 1;              // 0..127
    const int kc = (tid & 1) * 2;         // chunk pair 0-1 or 2-3
    const __half* Ah = A + (size_t)(row0 + r1) * (2 * K) + kc * 8;
    const __half* Al = Ah + K;
    const __half* Bg = B + (size_t)(col0 + r1) * K + kc * 8;
    const uint32_t sd = (uint32_t)(r1 * SPITCH + kc * 16);

    // ---- ldmatrix lane offsets (within stage) ----
    const uint32_t aoff =
        (uint32_t)((warpM * 64 + (lane & 7) + ((lane >> 3) & 1) * 8) * SPITCH +
                   ((lane >> 4) & 1) * 16);
    const uint32_t boff =
        (uint32_t)(2 * TILEB +
                   (warpN * 32 + (lane & 7) + ((lane >> 4) & 1) * 8) * SPITCH +
                   ((lane >> 3) & 1) * 16);

    float acc[16][4];
#pragma unroll
    for (int i = 0; i < 16; i++)
#pragma unroll
        for (int j = 0; j < 4; j++) acc[i][j] = 0.f;

    const int T = K >> 5;

    // prologue: stages 0,1
#pragma unroll
    for (int s = 0; s < 2; s++) {
        const uint32_t sb = smu + s * STAGEB;
        const size_t ko = (size_t)s * 32;
        cp16(sb + sd,                Ah + ko);
        cp16(sb + sd + 16,           Ah + ko + 8);
        cp16(sb + TILEB + sd,        Al + ko);
        cp16(sb + TILEB + sd + 16,   Al + ko + 8);
        cp16(sb + 2 * TILEB + sd,      Bg + ko);
        cp16(sb + 2 * TILEB + sd + 16, Bg + ko + 8);
        CP_COMMIT();
    }

    for (int kt = 0; kt < T; ++kt) {
        CP_WAIT1();
        __syncthreads();

        if (kt + 2 < T) {
            const uint32_t sb = smu + ((kt + 2) % 3) * STAGEB;
            const size_t ko = (size_t)(kt + 2) * 32;
            cp16(sb + sd,                Ah + ko);
            cp16(sb + sd + 16,           Ah + ko + 8);
            cp16(sb + TILEB + sd,        Al + ko);
            cp16(sb + TILEB + sd + 16,   Al + ko + 8);
            cp16(sb + 2 * TILEB + sd,      Bg + ko);
            cp16(sb + 2 * TILEB + sd + 16, Bg + ko + 8);
        }
        CP_COMMIT();

        const uint32_t base = smu + (kt % 3) * STAGEB;
#pragma unroll
        for (int kk = 0; kk < 2; kk++) {
            uint32_t bf[4][2];
#pragma unroll
            for (int p = 0; p < 2; p++)
                ldmx4(base + boff + p * 16 * SPITCH + kk * 32,
                      bf[2 * p][0], bf[2 * p][1], bf[2 * p + 1][0], bf[2 * p + 1][1]);
#pragma unroll
            for (int mt = 0; mt < 4; mt++) {
                uint32_t af[4];
                // A_hi
                ldmx4(base + aoff + mt * 16 * SPITCH + kk * 32,
                      af[0], af[1], af[2], af[3]);
#pragma unroll
                for (int nt = 0; nt < 4; nt++)
                    mma16816(acc[mt * 4 + nt], af, bf[nt]);
                // A_lo against the SAME B fragments
                ldmx4(base + TILEB + aoff + mt * 16 * SPITCH + kk * 32,
                      af[0], af[1], af[2], af[3]);
#pragma unroll
                for (int nt = 0; nt < 4; nt++)
                    mma16816(acc[mt * 4 + nt], af, bf[nt]);
            }
        }
    }

    // ------------------------------ epilogue --------------------------------
#pragma unroll
    for (int mt = 0; mt < 4; mt++) {
#pragma unroll
        for (int nt = 0; nt < 4; nt++) {
            const float* c = acc[mt * 4 + nt];
            const int col = col0 + warpN * 32 + nt * 8 + (lane & 3) * 2;
#pragma unroll
            for (int half = 0; half < 2; half++) {
                const int row = row0 + warpM * 64 + mt * 16 + (lane >> 2) + half * 8;
                const float v0 = c[half * 2 + 0], v1 = c[half * 2 + 1];
                if (MODE == 0) {
                    const int which = col >> 10, rem = col & 1023;
                    const float* bs = (which == 0) ? bias : (which == 2) ? bias2 : nullptr;
                    const float b0 = bs ? bs[rem] : 0.f, b1 = bs ? bs[rem + 1] : 0.f;
                    float* dst = g_qkv + (size_t)which * 33554432 +
                                 (size_t)(row >> 6) * 65536 + (rem >> 6) * 4096 +
                                 (row & 63) * 64 + (rem & 63);
                    *(float2*)dst = make_float2(v0 + b0, v1 + b1);
                } else if (MODE == 2) {
                    float s0 = v0 + bias[col], s1 = v1 + bias[col + 1];
                    s0 = 0.5f * s0 * (1.0f + erff(s0 * 0.70710678118654752f));
                    s1 = 0.5f * s1 * (1.0f + erff(s1 * 0.70710678118654752f));
                    __half h0, l0, h1, l1;
                    hf_split(s0, h0, l0);
                    hf_split(s1, h1, l1);
                    __half2 hh, ll;
                    hh.x = h0; hh.y = h1; ll.x = l0; ll.y = l1;
                    __half* dst = g_h2 + (size_t)row * 8192 + col;
                    *(__half2*)(dst) = hh;
                    *(__half2*)(dst + 4096) = ll;
                } else {
                    float* dst = Cf + (size_t)row * N + col;
                    *(float2*)dst = make_float2(v0 + bias[col], v1 + bias[col + 1]);
                }
            }
        }
    }
}

// ------------------------- split / gather kernels ---------------------------
// A-order: [hi | lo]; gathers x via winmap
__global__ void __launch_bounds__(256) xsplit_kernel(const float* __restrict__ x)
{
    const int wr = blockIdx.x;
    const int g = winmap(wr);
    const float4 v = *(const float4*)(x + (size_t)g * 1024 + threadIdx.x * 4);
    const float f[4] = {v.x, v.y, v.z, v.w};
    __half h[4], l[4];
#pragma unroll
    for (int j = 0; j < 4; j++) hf_split(f[j], h[j], l[j]);
    __half* dst = g_xg2 + (size_t)wr * 2048 + threadIdx.x * 4;
    __half2 h01, h23, l01, l23;
    h01.x = h[0]; h01.y = h[1]; h23.x = h[2]; h23.y = h[3];
    l01.x = l[0]; l01.y = l[1]; l23.x = l[2]; l23.y = l[3];
    *(__half2*)(dst) = h01;          *(__half2*)(dst + 2) = h23;
    *(__half2*)(dst + 1024) = l01;   *(__half2*)(dst + 1026) = l23;
}

// B: hi only, single copy
__global__ void __launch_bounds__(256) wsplit_kernel(
    const float* __restrict__ src, __half* __restrict__ dst, int K)
{
    const int row = blockIdx.x;
    const float* s = src + (size_t)row * K;
    __half* d = dst + (size_t)row * K;
    for (int c = threadIdx.x * 4; c < K; c += 1024) {
        const float4 v = *(const float4*)(s + c);
        __half2 h01, h23;
        h01.x = __float2half_rn(v.x); h01.y = __float2half_rn(v.y);
        h23.x = __float2half_rn(v.z); h23.y = __float2half_rn(v.w);
        *(__half2*)(d + c) = h01;
        *(__half2*)(d + c + 2) = h23;
    }
}

// --------------------------- CPB bias table ---------------------------------
__global__ void cpb_kernel(const float* __restrict__ w1,
                           const float* __restrict__ b1,
                           const float* __restrict__ w2)
{
    __shared__ float hbuf[512];
    const int p = blockIdx.x;
    const int a = p / 15, b = p % 15;
    const float va = (a - 7) * (1.0f / 7.0f), vb = (b - 7) * (1.0f / 7.0f);
    const float c0 = (va > 0.f ? 1.f : (va < 0.f ? -1.f : 0.f)) * log2f(1.f + fabsf(va));
    const float c1 = (vb > 0.f ? 1.f : (vb < 0.f ? -1.f : 0.f)) * log2f(1.f + fabsf(vb));
    const int j = threadIdx.x;
    float hv = w1[j * 2] * c0 + w1[j * 2 + 1] * c1 + b1[j];
    hbuf[j] = fmaxf(hv, 0.f);
    __syncthreads();
    if (j < 16) {
        float s = 0.f;
        for (int t = 0; t < 512; t++) s += hbuf[t] * w2[j * 512 + t];
        g_tbl[p * 16 + j] = 16.f / (1.f + expf(-s));
    }
}

// ------------------------------ attention -----------------------------------
__global__ void __launch_bounds__(256) attn_kernel(const float* __restrict__ ls)
{
    __shared__ float sA[64 * 68];
    __shared__ float sB[64 * 65];
    __shared__ float rn[128];

    const int h = blockIdx.x, wt = blockIdx.y;
    const int tid = threadIdx.x;
    const float* qg = g_qkv + (size_t)wt * 65536 + h * 4096;
    const float* kg = qg + 33554432;
    const float* vg = qg + 67108864;

#pragma unroll
    for (int i = 0; i < 4; i++) {
        int v4 = tid + 256 * i;
        int r = v4 >> 4, c4 = v4 & 15;
        *(float4*)&sA[r * 68 + c4 * 4] = *(const float4*)(qg + v4 * 4);
    }
#pragma unroll
    for (int i = 0; i < 16; i++) {
        int idx = tid + 256 * i;
        sB[(idx >> 6) * 65 + (idx & 63)] = kg[idx];
    }
    __syncthreads();

    {
        const int r = tid >> 2, part = tid & 3;
        float sq = 0.f, sk = 0.f;
#pragma unroll
        for (int j = 0; j < 16; j++) {
            float xq = sA[r * 68 + part + 4 * j]; sq += xq * xq;
            float xk = sB[r * 65 + part + 4 * j]; sk += xk * xk;
        }
        sq += __shfl_xor_sync(0xffffffffu, sq, 1);
        sq += __shfl_xor_sync(0xffffffffu, sq, 2);
        sk += __shfl_xor_sync(0xffffffffu, sk, 1);
        sk += __shfl_xor_sync(0xffffffffu, sk, 2);
        if (part == 0) {
            rn[r]      = 1.f / fmaxf(sqrtf(sq), 1e-12f);
            rn[64 + r] = 1.f / fmaxf(sqrtf(sk), 1e-12f);
        }
    }
    __syncthreads();

    const float scale = expf(fminf(ls[h], LN100));
    const int wi = wt & 3;
    const int m = tid & 63;
    const int nbase = tid >> 6;

    float kreg[64];
#pragma unroll
    for (int kk = 0; kk < 64; kk++) kreg[kk] = sB[m * 65 + kk];

    const int srm = ((wi >> 1) << 3) + (m >> 3), scm = ((wi & 1) << 3) + (m & 7);
    const int rgm = (srm < 8 ? 0 : (srm < 12 ? 1 : 2)) * 3 +
                    (scm < 8 ? 0 : (scm < 12 ? 1 : 2));

    float sc[16];
#pragma unroll
    for (int i = 0; i < 16; i++) {
        const int n = nbase + 4 * i;
        float dot = 0.f;
#pragma unroll
        for (int k4 = 0; k4 < 16; k4++) {
            float4 qv = *(const float4*)&sA[n * 68 + k4 * 4];
            dot += qv.x * kreg[k4 * 4] + qv.y * kreg[k4 * 4 + 1] +
                   qv.z * kreg[k4 * 4 + 2] + qv.w * kreg[k4 * 4 + 3];
        }
        dot *= rn[n] * rn[64 + m] * scale;
        const int idx = ((n >> 3) - (m >> 3) + 7) * 15 + ((n & 7) - (m & 7) + 7);
        dot += g_tbl[idx * 16 + h];
        const int srn = ((wi >> 1) << 3) + (n >> 3), scn = ((wi & 1) << 3) + (n & 7);
        const int rgn = (srn < 8 ? 0 : (srn < 12 ? 1 : 2)) * 3 +
                        (scn < 8 ? 0 : (scn < 12 ? 1 : 2));
        if (rgn != rgm) dot -= 100.f;
        sc[i] = dot;
    }
    __syncthreads();

#pragma unroll
    for (int i = 0; i < 16; i++) sA[(nbase + 4 * i) * 68 + m] = sc[i];
#pragma unroll
    for (int i = 0; i < 16; i++) {
        int idx = tid + 256 * i;
        sB[(idx >> 6) * 65 + (idx & 63)] = vg[idx];
    }
    __syncthreads();

    {
        const int r = tid >> 2, part = tid & 3;
        float mx = -1e30f;
#pragma unroll
        for (int j = 0; j < 16; j++) mx = fmaxf(mx, sA[r * 68 + part + 4 * j]);
        mx = fmaxf(mx, __shfl_xor_sync(0xffffffffu, mx, 1));
        mx = fmaxf(mx, __shfl_xor_sync(0xffffffffu, mx, 2));
        float sum = 0.f;
#pragma unroll
        for (int j = 0; j < 16; j++) {
            float e = expf(sA[r * 68 + part + 4 * j] - mx);
            sA[r * 68 + part + 4 * j] = e;
            sum += e;
        }
        sum += __shfl_xor_sync(0xffffffffu, sum, 1);
        sum += __shfl_xor_sync(0xffffffffu, sum, 2);
        const float inv = 1.f / sum;
#pragma unroll
        for (int j = 0; j < 16; j++) sA[r * 68 + part + 4 * j] *= inv;
    }
    __syncthreads();

    const int d = tid & 63;
    float vreg[64];
#pragma unroll
    for (int mm = 0; mm < 64; mm++) vreg[mm] = sB[mm * 65 + d];
#pragma unroll
    for (int i = 0; i < 16; i++) {
        const int n = nbase + 4 * i;
        float o = 0.f;
#pragma unroll
        for (int m4 = 0; m4 < 16; m4++) {
            float4 pv = *(const float4*)&sA[n * 68 + m4 * 4];
            o += pv.x * vreg[m4 * 4] + pv.y * vreg[m4 * 4 + 1] +
                 pv.z * vreg[m4 * 4 + 2] + pv.w * vreg[m4 * 4 + 3];
        }
        __half hi, lo;
        hf_split(o, hi, lo);
        const size_t base = (size_t)(wt * 64 + n) * 2048 + h * 64 + d;
        g_attn2[base] = hi;
        g_attn2[base + 1024] = lo;
    }
}

// --------------------------- LN kernels --------------------------------------
__device__ __forceinline__ float2 block_reduce2(float s, float q, float* red)
{
#pragma unroll
    for (int o = 16; o; o >>= 1) {
        s += __shfl_xor_sync(0xffffffffu, s, o);
        q += __shfl_xor_sync(0xffffffffu, q, o);
    }
    const int w = threadIdx.x >> 5;
    if ((threadIdx.x & 31) == 0) { red[w] = s; red[8 + w] = q; }
    __syncthreads();
    s = red[threadIdx.x & 7];
    q = red[8 + (threadIdx.x & 7)];
#pragma unroll
    for (int o = 4; o; o >>= 1) {
        s += __shfl_xor_sync(0xffffffffu, s, o);
        q += __shfl_xor_sync(0xffffffffu, q, o);
    }
    return make_float2(s, q);
}

// xs1[g] = x[g] + LN(proj[wr]); also emits fp16 split rows for fc1 A
__global__ void __launch_bounds__(256) lnscatter_kernel(
    const float* __restrict__ x, const float* __restrict__ w,
    const float* __restrict__ b, float* __restrict__ out)
{
    __shared__ float red[16];
    const int wr = blockIdx.x;
    const int g = winmap(wr);
    const float* p = g_proj + (size_t)wr * 1024;
    float vv[4], s = 0.f, q = 0.f;
#pragma unroll
    for (int i = 0; i < 4; i++) {
        vv[i] = p[threadIdx.x + 256 * i];
        s += vv[i]; q += vv[i] * vv[i];
    }
    float2 t = block_reduce2(s, q, red);
    const float mean = t.x * (1.f / 1024.f);
    const float var = t.y * (1.f / 1024.f) - mean * mean;
    const float rs = rsqrtf(var + 1e-5f);
    const float* xr = x + (size_t)g * 1024;
    float* orow = out + (size_t)g * 1024;
    __half* drow = g_out2 + (size_t)g * 2048;
#pragma unroll
    for (int i = 0; i < 4; i++) {
        const int c = threadIdx.x + 256 * i;
        const float val = xr[c] + (vv[i] - mean) * rs * w[c] + b[c];
        orow[c] = val;
        __half hi, lo;
        hf_split(val, hi, lo);
        drow[c] = hi;
        drow[1024 + c] = lo;
    }
}

// out[tok] += LN(mlp[tok])
__global__ void __launch_bounds__(256) lnadd_kernel(
    const float* __restrict__ w, const float* __restrict__ b,
    float* __restrict__ out)
{
    __shared__ float red[16];
    const int tok = blockIdx.x;
    const float* p = g_mlp + (size_t)tok * 1024;
    float vv[4], s = 0.f, q = 0.f;
#pragma unroll
    for (int i = 0; i < 4; i++) {
        vv[i] = p[threadIdx.x + 256 * i];
        s += vv[i]; q += vv[i] * vv[i];
    }
    float2 t = block_reduce2(s, q, red);
    const float mean = t.x * (1.f / 1024.f);
    const float var = t.y * (1.f / 1024.f) - mean * mean;
    const float rs = rsqrtf(var + 1e-5f);
    float* orow = out + (size_t)tok * 1024;
#pragma unroll
    for (int i = 0; i < 4; i++) {
        const int c = threadIdx.x + 256 * i;
        orow[c] += (vv[i] - mean) * rs * w[c] + b[c];
    }
}

// ------------------------------- launcher -----------------------------------
extern "C" void kernel_launch(void* const* d_in, const int* in_sizes, int n_in,
                              void* d_out, int out_size)
{
    const float* x      = (const float*)d_in[0];
    const float* qkv_w  = (const float*)d_in[1];
    const float* q_bias = (const float*)d_in[2];
    const float* v_bias = (const float*)d_in[3];
    const float* lscale = (const float*)d_in[4];
    const float* cpb_w1 = (const float*)d_in[5];
    const float* cpb_b1 = (const float*)d_in[6];
    const float* cpb_w2 = (const float*)d_in[7];
    const float* proj_w = (const float*)d_in[8];
    const float* proj_b = (const float*)d_in[9];
    const float* n1w    = (const float*)d_in[10];
    const float* n1b    = (const float*)d_in[11];
    const float* fc1_w  = (const float*)d_in[12];
    const float* fc1_b  = (const float*)d_in[13];
    const float* fc2_w  = (const float*)d_in[14];
    const float* fc2_b  = (const float*)d_in[15];
    const float* n2w    = (const float*)d_in[16];
    const float* n2b    = (const float*)d_in[17];
    float* out = (float*)d_out;

    __half *p_xg2, *p_w2, *p_attn2, *p_out2, *p_h2;
    float *p_proj, *p_mlp;
    cudaGetSymbolAddress((void**)&p_xg2,   g_xg2);
    cudaGetSymbolAddress((void**)&p_w2,    g_w2);
    cudaGetSymbolAddress((void**)&p_attn2, g_attn2);
    cudaGetSymbolAddress((void**)&p_out2,  g_out2);
    cudaGetSymbolAddress((void**)&p_h2,    g_h2);
    cudaGetSymbolAddress((void**)&p_proj,  g_proj);
    cudaGetSymbolAddress((void**)&p_mlp,   g_mlp);

    const int SMEMSZ = 3 * STAGEB;  // 92160
    cudaFuncSetAttribute(mma_gemm<0>, cudaFuncAttributeMaxDynamicSharedMemorySize, SMEMSZ);
    cudaFuncSetAttribute(mma_gemm<1>, cudaFuncAttributeMaxDynamicSharedMemorySize, SMEMSZ);
    cudaFuncSetAttribute(mma_gemm<2>, cudaFuncAttributeMaxDynamicSharedMemorySize, SMEMSZ);
    cudaFuncSetAttribute(mma_gemm<3>, cudaFuncAttributeMaxDynamicSharedMemorySize, SMEMSZ);

    cpb_kernel<<<225, 512>>>(cpb_w1, cpb_b1, cpb_w2);
    xsplit_kernel<<<32768, 256>>>(x);
    wsplit_kernel<<<3072, 256>>>(qkv_w, p_w2 + W2_QKV, 1024);
    wsplit_kernel<<<1024, 256>>>(proj_w, p_w2 + W2_PROJ, 1024);
    wsplit_kernel<<<4096, 256>>>(fc1_w, p_w2 + W2_FC1, 1024);
    wsplit_kernel<<<1024, 256>>>(fc2_w, p_w2 + W2_FC2, 4096);

    // QKV: M=32768, N=3072, K=1024
    mma_gemm<0><<<dim3(24, 256), 256, SMEMSZ>>>(
        p_xg2, p_w2 + W2_QKV, q_bias, v_bias, nullptr, 1024, 3072);

    attn_kernel<<<dim3(16, 512), 256>>>(lscale);

    // proj: N=1024, K=1024
    mma_gemm<1><<<dim3(8, 256), 256, SMEMSZ>>>(
        p_attn2, p_w2 + W2_PROJ, proj_b, nullptr, p_proj, 1024, 1024);

    lnscatter_kernel<<<32768, 256>>>(x, n1w, n1b, out);

    // fc1 + GELU: N=4096, K=1024
    mma_gemm<2><<<dim3(32, 256), 256, SMEMSZ>>>(
        p_out2, p_w2 + W2_FC1, fc1_b, nullptr, nullptr, 1024, 4096);

    // fc2: N=1024, K=4096
    mma_gemm<3><<<dim3(8, 256), 256, SMEMSZ>>>(
        p_h2, p_w2 + W2_FC2, fc2_b, nullptr, p_mlp, 4096, 1024);

    lnadd_kernel<<<32768, 256>>>(n2w, n2b, out);
}

// round 9
// speedup vs baseline: 1.8976x; 1.7193x over previous
#include <cuda_runtime.h>
#include <cuda_fp16.h>
#include <math.h>
#include <stdint.h>

// ===========================================================================
// SwinV2 block. GEMMs via mma.sync (HMMA) pure fp16 x fp16, fp32 accum.
// CTA 128x128, 8 warps of 64x32, 3-stage cp.async, 2 CTAs/SM.
// Error budget: A+B fp16 rounding ~ sqrt(2) x 3.49e-4 ~ 4.9e-4 < 1e-3.
// ===========================================================================

#define LN100 4.6051701859880914f

// ------------------------- scratch (device globals) ------------------------
__device__ __align__(128) __half g_xg[33554432];     // [32768][1024] A qkv
__device__ __align__(128) __half g_w2[12582912];     // weights fp16
__device__ __align__(128) __half g_attn2[33554432];  // [32768][1024] A proj
__device__ __align__(128) __half g_out2[33554432];   // [32768][1024] A fc1
__device__ __align__(128) __half g_h2[134217728];    // [32768][4096] A fc2
__device__ __align__(128) float g_qkv[100663296];    // [3][512][16][64][64]
__device__ __align__(128) float g_proj[33554432];
__device__ __align__(128) float g_mlp[33554432];
__device__ float g_tbl[3600];

#define W2_QKV  0
#define W2_PROJ 3145728
#define W2_FC1  4194304
#define W2_FC2  8388608

__device__ __forceinline__ int winmap(int wr) {
    int wt = wr >> 6, t = wr & 63;
    int img = wt >> 2, wi = wt & 3;
    int r = (((wi >> 1) << 3) + (t >> 3) + 4) & 15;
    int c = (((wi & 1) << 3) + (t & 7) + 4) & 15;
    return (img << 8) + (r << 4) + c;
}

// ---------------------------- PTX helpers -----------------------------------
__device__ __forceinline__ uint32_t smem_u32(const void* p) {
    uint32_t a;
    asm("{ .reg .u64 t; cvta.to.shared.u64 t, %1; cvt.u32.u64 %0, t; }"
        : "=r"(a) : "l"(p));
    return a;
}
__device__ __forceinline__ void cp16(uint32_t s, const void* g) {
    asm volatile("cp.async.cg.shared.global [%0], [%1], 16;" :: "r"(s), "l"(g));
}
#define CP_COMMIT() asm volatile("cp.async.commit_group;" ::: "memory")
#define CP_WAIT1()  asm volatile("cp.async.wait_group 1;" ::: "memory")

__device__ __forceinline__ void ldmx4(uint32_t a, uint32_t& r0, uint32_t& r1,
                                      uint32_t& r2, uint32_t& r3) {
    asm volatile("ldmatrix.sync.aligned.m8n8.x4.shared.b16 {%0,%1,%2,%3}, [%4];"
                 : "=r"(r0), "=r"(r1), "=r"(r2), "=r"(r3) : "r"(a));
}
__device__ __forceinline__ void mma16816(float* c, const uint32_t* a,
                                         const uint32_t* b) {
    asm volatile(
        "mma.sync.aligned.m16n8k16.row.col.f32.f16.f16.f32 "
        "{%0,%1,%2,%3}, {%4,%5,%6,%7}, {%8,%9}, {%0,%1,%2,%3};"
        : "+f"(c[0]), "+f"(c[1]), "+f"(c[2]), "+f"(c[3])
        : "r"(a[0]), "r"(a[1]), "r"(a[2]), "r"(a[3]), "r"(b[0]), "r"(b[1]));
}

// ------------------------------- HMMA GEMM ----------------------------------
// C[M,N] = A[M,K] * B[N,K]^T, both fp16 row-major (K contiguous).
// CTA 128x128, BK=32, 3 stages cp.async, 8 warps of 64x32, 2 CTAs/SM.
// MODE 0: QKV scatter (+q/v bias) -> g_qkv fp32
// MODE 1: +bias -> Cf fp32
// MODE 2: +bias +exact GELU -> g_h2 fp16
// MODE 3: +bias -> Cf fp32
#define SPITCH 80
#define ATILE  10240           // 128*80
#define STAGEB 20480           // A + B

template <int MODE>
__global__ void __launch_bounds__(256, 2) mma_gemm(
    const __half* __restrict__ A, const __half* __restrict__ B,
    const float* __restrict__ bias, const float* __restrict__ bias2,
    float* __restrict__ Cf, int K, int N)
{
    extern __shared__ __align__(128) char sm[];
    const uint32_t smu = smem_u32(sm);
    const int tid = threadIdx.x;
    const int lane = tid & 31, w = tid >> 5;
    const int warpM = w >> 2, warpN = w & 3;
    const int row0 = blockIdx.y * 128, col0 = blockIdx.x * 128;

    // ---- cp.async assignment: thread covers rows r1 and r1+64, chunk kc ----
    const int r1 = tid >> 2, kc = tid & 3;
    const __half* Ag0 = A + (size_t)(row0 + r1) * K + kc * 8;
    const __half* Ag1 = Ag0 + (size_t)64 * K;
    const __half* Bg0 = B + (size_t)(col0 + r1) * K + kc * 8;
    const __half* Bg1 = Bg0 + (size_t)64 * K;
    const uint32_t sd0 = (uint32_t)(r1 * SPITCH + kc * 16);
    const uint32_t sd1 = sd0 + 64 * SPITCH;

    // ---- ldmatrix lane offsets (within stage) ----
    const uint32_t aoff =
        (uint32_t)((warpM * 64 + (lane & 7) + ((lane >> 3) & 1) * 8) * SPITCH +
                   ((lane >> 4) & 1) * 16);
    const uint32_t boff =
        (uint32_t)(ATILE + (warpN * 32 + (lane & 7) + ((lane >> 4) & 1) * 8) * SPITCH +
                   ((lane >> 3) & 1) * 16);

    float acc[16][4];
#pragma unroll
    for (int i = 0; i < 16; i++)
#pragma unroll
        for (int j = 0; j < 4; j++) acc[i][j] = 0.f;

    const int T = K >> 5;

    // prologue: stages 0,1
#pragma unroll
    for (int s = 0; s < 2; s++) {
        const uint32_t sb = smu + s * STAGEB;
        const size_t ko = (size_t)s * 32;
        cp16(sb + sd0, Ag0 + ko);
        cp16(sb + sd1, Ag1 + ko);
        cp16(sb + ATILE + sd0, Bg0 + ko);
        cp16(sb + ATILE + sd1, Bg1 + ko);
        CP_COMMIT();
    }

    for (int kt = 0; kt < T; ++kt) {
        CP_WAIT1();
        __syncthreads();

        if (kt + 2 < T) {
            const uint32_t sb = smu + ((kt + 2) % 3) * STAGEB;
            const size_t ko = (size_t)(kt + 2) * 32;
            cp16(sb + sd0, Ag0 + ko);
            cp16(sb + sd1, Ag1 + ko);
            cp16(sb + ATILE + sd0, Bg0 + ko);
            cp16(sb + ATILE + sd1, Bg1 + ko);
        }
        CP_COMMIT();

        const uint32_t base = smu + (kt % 3) * STAGEB;
#pragma unroll
        for (int kk = 0; kk < 2; kk++) {
            uint32_t bf[4][2];
#pragma unroll
            for (int p = 0; p < 2; p++)
                ldmx4(base + boff + p * 16 * SPITCH + kk * 32,
                      bf[2 * p][0], bf[2 * p][1], bf[2 * p + 1][0], bf[2 * p + 1][1]);
#pragma unroll
            for (int mt = 0; mt < 4; mt++) {
                uint32_t af[4];
                ldmx4(base + aoff + mt * 16 * SPITCH + kk * 32,
                      af[0], af[1], af[2], af[3]);
#pragma unroll
                for (int nt = 0; nt < 4; nt++)
                    mma16816(acc[mt * 4 + nt], af, bf[nt]);
            }
        }
    }

    // ------------------------------ epilogue --------------------------------
#pragma unroll
    for (int mt = 0; mt < 4; mt++) {
#pragma unroll
        for (int nt = 0; nt < 4; nt++) {
            const float* c = acc[mt * 4 + nt];
            const int col = col0 + warpN * 32 + nt * 8 + (lane & 3) * 2;
#pragma unroll
            for (int half = 0; half < 2; half++) {
                const int row = row0 + warpM * 64 + mt * 16 + (lane >> 2) + half * 8;
                const float v0 = c[half * 2 + 0], v1 = c[half * 2 + 1];
                if (MODE == 0) {
                    const int which = col >> 10, rem = col & 1023;
                    const float* bs = (which == 0) ? bias : (which == 2) ? bias2 : nullptr;
                    const float b0 = bs ? bs[rem] : 0.f, b1 = bs ? bs[rem + 1] : 0.f;
                    float* dst = g_qkv + (size_t)which * 33554432 +
                                 (size_t)(row >> 6) * 65536 + (rem >> 6) * 4096 +
                                 (row & 63) * 64 + (rem & 63);
                    *(float2*)dst = make_float2(v0 + b0, v1 + b1);
                } else if (MODE == 2) {
                    float s0 = v0 + bias[col], s1 = v1 + bias[col + 1];
                    s0 = 0.5f * s0 * (1.0f + erff(s0 * 0.70710678118654752f));
                    s1 = 0.5f * s1 * (1.0f + erff(s1 * 0.70710678118654752f));
                    __half2 hh;
                    hh.x = __float2half_rn(s0);
                    hh.y = __float2half_rn(s1);
                    *(__half2*)(g_h2 + (size_t)row * 4096 + col) = hh;
                } else {
                    float* dst = Cf + (size_t)row * N + col;
                    *(float2*)dst = make_float2(v0 + bias[col], v1 + bias[col + 1]);
                }
            }
        }
    }
}

// ------------------------- convert / gather kernels --------------------------
// gathers x via winmap, fp16
__global__ void __launch_bounds__(256) xconv_kernel(const float* __restrict__ x)
{
    const int wr = blockIdx.x;
    const int g = winmap(wr);
    const float4 v = *(const float4*)(x + (size_t)g * 1024 + threadIdx.x * 4);
    __half2 h01, h23;
    h01.x = __float2half_rn(v.x); h01.y = __float2half_rn(v.y);
    h23.x = __float2half_rn(v.z); h23.y = __float2half_rn(v.w);
    __half* dst = g_xg + (size_t)wr * 1024 + threadIdx.x * 4;
    *(__half2*)(dst) = h01;
    *(__half2*)(dst + 2) = h23;
}

// weights -> fp16
__global__ void __launch_bounds__(256) wconv_kernel(
    const float* __restrict__ src, __half* __restrict__ dst, int K)
{
    const int row = blockIdx.x;
    const float* s = src + (size_t)row * K;
    __half* d = dst + (size_t)row * K;
    for (int c = threadIdx.x * 4; c < K; c += 1024) {
        const float4 v = *(const float4*)(s + c);
        __half2 h01, h23;
        h01.x = __float2half_rn(v.x); h01.y = __float2half_rn(v.y);
        h23.x = __float2half_rn(v.z); h23.y = __float2half_rn(v.w);
        *(__half2*)(d + c) = h01;
        *(__half2*)(d + c + 2) = h23;
    }
}

// --------------------------- CPB bias table ---------------------------------
__global__ void cpb_kernel(const float* __restrict__ w1,
                           const float* __restrict__ b1,
                           const float* __restrict__ w2)
{
    __shared__ float hbuf[512];
    const int p = blockIdx.x;
    const int a = p / 15, b = p % 15;
    const float va = (a - 7) * (1.0f / 7.0f), vb = (b - 7) * (1.0f / 7.0f);
    const float c0 = (va > 0.f ? 1.f : (va < 0.f ? -1.f : 0.f)) * log2f(1.f + fabsf(va));
    const float c1 = (vb > 0.f ? 1.f : (vb < 0.f ? -1.f : 0.f)) * log2f(1.f + fabsf(vb));
    const int j = threadIdx.x;
    float hv = w1[j * 2] * c0 + w1[j * 2 + 1] * c1 + b1[j];
    hbuf[j] = fmaxf(hv, 0.f);
    __syncthreads();
    if (j < 16) {
        float s = 0.f;
        for (int t = 0; t < 512; t++) s += hbuf[t] * w2[j * 512 + t];
        g_tbl[p * 16 + j] = 16.f / (1.f + expf(-s));
    }
}

// ------------------------------ attention -----------------------------------
__global__ void __launch_bounds__(256) attn_kernel(const float* __restrict__ ls)
{
    __shared__ float sA[64 * 68];
    __shared__ float sB[64 * 65];
    __shared__ float rn[128];

    const int h = blockIdx.x, wt = blockIdx.y;
    const int tid = threadIdx.x;
    const float* qg = g_qkv + (size_t)wt * 65536 + h * 4096;
    const float* kg = qg + 33554432;
    const float* vg = qg + 67108864;

#pragma unroll
    for (int i = 0; i < 4; i++) {
        int v4 = tid + 256 * i;
        int r = v4 >> 4, c4 = v4 & 15;
        *(float4*)&sA[r * 68 + c4 * 4] = *(const float4*)(qg + v4 * 4);
    }
#pragma unroll
    for (int i = 0; i < 16; i++) {
        int idx = tid + 256 * i;
        sB[(idx >> 6) * 65 + (idx & 63)] = kg[idx];
    }
    __syncthreads();

    {
        const int r = tid >> 2, part = tid & 3;
        float sq = 0.f, sk = 0.f;
#pragma unroll
        for (int j = 0; j < 16; j++) {
            float xq = sA[r * 68 + part + 4 * j]; sq += xq * xq;
            float xk = sB[r * 65 + part + 4 * j]; sk += xk * xk;
        }
        sq += __shfl_xor_sync(0xffffffffu, sq, 1);
        sq += __shfl_xor_sync(0xffffffffu, sq, 2);
        sk += __shfl_xor_sync(0xffffffffu, sk, 1);
        sk += __shfl_xor_sync(0xffffffffu, sk, 2);
        if (part == 0) {
            rn[r]      = 1.f / fmaxf(sqrtf(sq), 1e-12f);
            rn[64 + r] = 1.f / fmaxf(sqrtf(sk), 1e-12f);
        }
    }
    __syncthreads();

    const float scale = expf(fminf(ls[h], LN100));
    const int wi = wt & 3;
    const int m = tid & 63;
    const int nbase = tid >> 6;

    float kreg[64];
#pragma unroll
    for (int kk = 0; kk < 64; kk++) kreg[kk] = sB[m * 65 + kk];

    const int srm = ((wi >> 1) << 3) + (m >> 3), scm = ((wi & 1) << 3) + (m & 7);
    const int rgm = (srm < 8 ? 0 : (srm < 12 ? 1 : 2)) * 3 +
                    (scm < 8 ? 0 : (scm < 12 ? 1 : 2));

    float sc[16];
#pragma unroll
    for (int i = 0; i < 16; i++) {
        const int n = nbase + 4 * i;
        float dot = 0.f;
#pragma unroll
        for (int k4 = 0; k4 < 16; k4++) {
            float4 qv = *(const float4*)&sA[n * 68 + k4 * 4];
            dot += qv.x * kreg[k4 * 4] + qv.y * kreg[k4 * 4 + 1] +
                   qv.z * kreg[k4 * 4 + 2] + qv.w * kreg[k4 * 4 + 3];
        }
        dot *= rn[n] * rn[64 + m] * scale;
        const int idx = ((n >> 3) - (m >> 3) + 7) * 15 + ((n & 7) - (m & 7) + 7);
        dot += g_tbl[idx * 16 + h];
        const int srn = ((wi >> 1) << 3) + (n >> 3), scn = ((wi & 1) << 3) + (n & 7);
        const int rgn = (srn < 8 ? 0 : (srn < 12 ? 1 : 2)) * 3 +
                        (scn < 8 ? 0 : (scn < 12 ? 1 : 2));
        if (rgn != rgm) dot -= 100.f;
        sc[i] = dot;
    }
    __syncthreads();

#pragma unroll
    for (int i = 0; i < 16; i++) sA[(nbase + 4 * i) * 68 + m] = sc[i];
#pragma unroll
    for (int i = 0; i < 16; i++) {
        int idx = tid + 256 * i;
        sB[(idx >> 6) * 65 + (idx & 63)] = vg[idx];
    }
    __syncthreads();

    {
        const int r = tid >> 2, part = tid & 3;
        float mx = -1e30f;
#pragma unroll
        for (int j = 0; j < 16; j++) mx = fmaxf(mx, sA[r * 68 + part + 4 * j]);
        mx = fmaxf(mx, __shfl_xor_sync(0xffffffffu, mx, 1));
        mx = fmaxf(mx, __shfl_xor_sync(0xffffffffu, mx, 2));
        float sum = 0.f;
#pragma unroll
        for (int j = 0; j < 16; j++) {
            float e = expf(sA[r * 68 + part + 4 * j] - mx);
            sA[r * 68 + part + 4 * j] = e;
            sum += e;
        }
        sum += __shfl_xor_sync(0xffffffffu, sum, 1);
        sum += __shfl_xor_sync(0xffffffffu, sum, 2);
        const float inv = 1.f / sum;
#pragma unroll
        for (int j = 0; j < 16; j++) sA[r * 68 + part + 4 * j] *= inv;
    }
    __syncthreads();

    const int d = tid & 63;
    float vreg[64];
#pragma unroll
    for (int mm = 0; mm < 64; mm++) vreg[mm] = sB[mm * 65 + d];
#pragma unroll
    for (int i = 0; i < 16; i++) {
        const int n = nbase + 4 * i;
        float o = 0.f;
#pragma unroll
        for (int m4 = 0; m4 < 16; m4++) {
            float4 pv = *(const float4*)&sA[n * 68 + m4 * 4];
            o += pv.x * vreg[m4 * 4] + pv.y * vreg[m4 * 4 + 1] +
                 pv.z * vreg[m4 * 4 + 2] + pv.w * vreg[m4 * 4 + 3];
        }
        g_attn2[(size_t)(wt * 64 + n) * 1024 + h * 64 + d] = __float2half_rn(o);
    }
}

// --------------------------- LN kernels --------------------------------------
__device__ __forceinline__ float2 block_reduce2(float s, float q, float* red)
{
#pragma unroll
    for (int o = 16; o; o >>= 1) {
        s += __shfl_xor_sync(0xffffffffu, s, o);
        q += __shfl_xor_sync(0xffffffffu, q, o);
    }
    const int w = threadIdx.x >> 5;
    if ((threadIdx.x & 31) == 0) { red[w] = s; red[8 + w] = q; }
    __syncthreads();
    s = red[threadIdx.x & 7];
    q = red[8 + (threadIdx.x & 7)];
#pragma unroll
    for (int o = 4; o; o >>= 1) {
        s += __shfl_xor_sync(0xffffffffu, s, o);
        q += __shfl_xor_sync(0xffffffffu, q, o);
    }
    return make_float2(s, q);
}

// xs1[g] = x[g] + LN(proj[wr]); also emits fp16 rows for fc1 A
__global__ void __launch_bounds__(256) lnscatter_kernel(
    const float* __restrict__ x, const float* __restrict__ w,
    const float* __restrict__ b, float* __restrict__ out)
{
    __shared__ float red[16];
    const int wr = blockIdx.x;
    const int g = winmap(wr);
    const float* p = g_proj + (size_t)wr * 1024;
    float vv[4], s = 0.f, q = 0.f;
#pragma unroll
    for (int i = 0; i < 4; i++) {
        vv[i] = p[threadIdx.x + 256 * i];
        s += vv[i]; q += vv[i] * vv[i];
    }
    float2 t = block_reduce2(s, q, red);
    const float mean = t.x * (1.f / 1024.f);
    const float var = t.y * (1.f / 1024.f) - mean * mean;
    const float rs = rsqrtf(var + 1e-5f);
    const float* xr = x + (size_t)g * 1024;
    float* orow = out + (size_t)g * 1024;
    __half* drow = g_out2 + (size_t)g * 1024;
#pragma unroll
    for (int i = 0; i < 4; i++) {
        const int c = threadIdx.x + 256 * i;
        const float val = xr[c] + (vv[i] - mean) * rs * w[c] + b[c];
        orow[c] = val;
        drow[c] = __float2half_rn(val);
    }
}

// out[tok] += LN(mlp[tok])
__global__ void __launch_bounds__(256) lnadd_kernel(
    const float* __restrict__ w, const float* __restrict__ b,
    float* __restrict__ out)
{
    __shared__ float red[16];
    const int tok = blockIdx.x;
    const float* p = g_mlp + (size_t)tok * 1024;
    float vv[4], s = 0.f, q = 0.f;
#pragma unroll
    for (int i = 0; i < 4; i++) {
        vv[i] = p[threadIdx.x + 256 * i];
        s += vv[i]; q += vv[i] * vv[i];
    }
    float2 t = block_reduce2(s, q, red);
    const float mean = t.x * (1.f / 1024.f);
    const float var = t.y * (1.f / 1024.f) - mean * mean;
    const float rs = rsqrtf(var + 1e-5f);
    float* orow = out + (size_t)tok * 1024;
#pragma unroll
    for (int i = 0; i < 4; i++) {
        const int c = threadIdx.x + 256 * i;
        orow[c] += (vv[i] - mean) * rs * w[c] + b[c];
    }
}

// ------------------------------- launcher -----------------------------------
extern "C" void kernel_launch(void* const* d_in, const int* in_sizes, int n_in,
                              void* d_out, int out_size)
{
    const float* x      = (const float*)d_in[0];
    const float* qkv_w  = (const float*)d_in[1];
    const float* q_bias = (const float*)d_in[2];
    const float* v_bias = (const float*)d_in[3];
    const float* lscale = (const float*)d_in[4];
    const float* cpb_w1 = (const float*)d_in[5];
    const float* cpb_b1 = (const float*)d_in[6];
    const float* cpb_w2 = (const float*)d_in[7];
    const float* proj_w = (const float*)d_in[8];
    const float* proj_b = (const float*)d_in[9];
    const float* n1w    = (const float*)d_in[10];
    const float* n1b    = (const float*)d_in[11];
    const float* fc1_w  = (const float*)d_in[12];
    const float* fc1_b  = (const float*)d_in[13];
    const float* fc2_w  = (const float*)d_in[14];
    const float* fc2_b  = (const float*)d_in[15];
    const float* n2w    = (const float*)d_in[16];
    const float* n2b    = (const float*)d_in[17];
    float* out = (float*)d_out;

    __half *p_xg, *p_w2, *p_attn2, *p_out2, *p_h2;
    float *p_proj, *p_mlp;
    cudaGetSymbolAddress((void**)&p_xg,    g_xg);
    cudaGetSymbolAddress((void**)&p_w2,    g_w2);
    cudaGetSymbolAddress((void**)&p_attn2, g_attn2);
    cudaGetSymbolAddress((void**)&p_out2,  g_out2);
    cudaGetSymbolAddress((void**)&p_h2,    g_h2);
    cudaGetSymbolAddress((void**)&p_proj,  g_proj);
    cudaGetSymbolAddress((void**)&p_mlp,   g_mlp);

    const int SMEMSZ = 3 * STAGEB;  // 61440
    cudaFuncSetAttribute(mma_gemm<0>, cudaFuncAttributeMaxDynamicSharedMemorySize, SMEMSZ);
    cudaFuncSetAttribute(mma_gemm<1>, cudaFuncAttributeMaxDynamicSharedMemorySize, SMEMSZ);
    cudaFuncSetAttribute(mma_gemm<2>, cudaFuncAttributeMaxDynamicSharedMemorySize, SMEMSZ);
    cudaFuncSetAttribute(mma_gemm<3>, cudaFuncAttributeMaxDynamicSharedMemorySize, SMEMSZ);

    // Launch order chosen so ncu (-s 5 -c 1) profiles the QKV GEMM (6th).
    wconv_kernel<<<3072, 256>>>(qkv_w, p_w2 + W2_QKV, 1024);
    wconv_kernel<<<1024, 256>>>(proj_w, p_w2 + W2_PROJ, 1024);
    wconv_kernel<<<4096, 256>>>(fc1_w, p_w2 + W2_FC1, 1024);
    wconv_kernel<<<1024, 256>>>(fc2_w, p_w2 + W2_FC2, 4096);
    xconv_kernel<<<32768, 256>>>(x);

    // QKV: M=32768, N=3072, K=1024   (6th launch — ncu target)
    mma_gemm<0><<<dim3(24, 256), 256, SMEMSZ>>>(
        p_xg, p_w2 + W2_QKV, q_bias, v_bias, nullptr, 1024, 3072);

    cpb_kernel<<<225, 512>>>(cpb_w1, cpb_b1, cpb_w2);
    attn_kernel<<<dim3(16, 512), 256>>>(lscale);

    // proj: N=1024, K=1024
    mma_gemm<1><<<dim3(8, 256), 256, SMEMSZ>>>(
        p_attn2, p_w2 + W2_PROJ, proj_b, nullptr, p_proj, 1024, 1024);

    lnscatter_kernel<<<32768, 256>>>(x, n1w, n1b, out);

    // fc1 + GELU: N=4096, K=1024
    mma_gemm<2><<<dim3(32, 256), 256, SMEMSZ>>>(
        p_out2, p_w2 + W2_FC1, fc1_b, nullptr, nullptr, 1024, 4096);

    // fc2: N=1024, K=4096
    mma_gemm<3><<<dim3(8, 256), 256, SMEMSZ>>>(
        p_h2, p_w2 + W2_FC2, fc2_b, nullptr, p_mlp, 4096, 1024);

    lnadd_kernel<<<32768, 256>>>(n2w, n2b, out);
}